// round 7
// baseline (speedup 1.0000x reference)
#include <cuda_runtime.h>
#include <cuda_bf16.h>
#include <cuda_fp16.h>
#include <cstdint>

#define G_NUM 1024
#define D 128

// ---------------------------------------------------------------------------
// Device scratch
// ---------------------------------------------------------------------------
__device__ int   g_segstart[G_NUM + 1];
__device__ float g_sums[G_NUM * D];
__device__ float g_C[G_NUM * D];
// W1 (fp16) in mma.sync B-fragment layout: ((ks*16 + na)*32 + lane)*2 + reg
__device__ __align__(16) uint32_t g_Bf[8192];

// ---------------------------------------------------------------------------
// Helpers
// ---------------------------------------------------------------------------
__device__ __forceinline__ uint32_t pack_f16(float lo, float hi) {
    uint32_t r;
    asm("cvt.rn.f16x2.f32 %0, %1, %2;" : "=r"(r) : "f"(hi), "f"(lo));
    return r;
}
__device__ __forceinline__ float lo_h(uint32_t p) {
    return __half2float(__ushort_as_half((unsigned short)(p & 0xffff)));
}
__device__ __forceinline__ float hi_h(uint32_t p) {
    return __half2float(__ushort_as_half((unsigned short)(p >> 16)));
}

__device__ __forceinline__ void mma_f16(float* d, const uint32_t* a, const uint32_t* b) {
    asm volatile(
        "mma.sync.aligned.m16n8k16.row.col.f32.f16.f16.f32 "
        "{%0,%1,%2,%3}, {%4,%5,%6,%7}, {%8,%9}, {%0,%1,%2,%3};"
        : "+f"(d[0]), "+f"(d[1]), "+f"(d[2]), "+f"(d[3])
        : "r"(a[0]), "r"(a[1]), "r"(a[2]), "r"(a[3]), "r"(b[0]), "r"(b[1]));
}

// ---------------------------------------------------------------------------
// K1: zero sums + segment boundaries + W1 -> fp16 B-fragments
// ---------------------------------------------------------------------------
__global__ void k_prep(const int* __restrict__ bid, int N, const float* __restrict__ W) {
    int i = blockIdx.x * blockDim.x + threadIdx.x;
    if (i < G_NUM * D) g_sums[i] = 0.f;
    if (i < N) {
        int b = bid[i];
        int prev = (i == 0) ? -1 : bid[i - 1];
        for (int g = prev + 1; g <= b; ++g) g_segstart[g] = i;
        if (i == N - 1)
            for (int g = b + 1; g <= G_NUM; ++g) g_segstart[g] = N;
    }
    if (i < 4096) {
        int ks = i >> 9;
        int na = (i >> 5) & 15;
        int l  = i & 31;
        int c  = l & 3;
        int n  = na * 8 + (l >> 2);
        int k0 = ks * 16 + 2 * c;
        const float* wr = W + (size_t)n * 256;
        g_Bf[i * 2 + 0] = pack_f16(wr[k0],     wr[k0 + 1]);
        g_Bf[i * 2 + 1] = pack_f16(wr[k0 + 8], wr[k0 + 9]);
    }
}

// ---------------------------------------------------------------------------
// K2: tile-parallel segment sums. CTA = 128 rows; 256 thr: thread owns
// feature (t&127) on rows (t>>7), (t>>7)+2, ... Flush at bid boundaries.
// ---------------------------------------------------------------------------
__global__ void __launch_bounds__(256)
k_sum(const float* __restrict__ x, const int* __restrict__ bid, int N) {
    __shared__ int sb[128];
    int tid = threadIdx.x;
    int n0 = blockIdx.x * 128;
    if (tid < 128) sb[tid] = (n0 + tid < N) ? bid[n0 + tid] : -1;
    __syncthreads();

    int half = tid >> 7;     // row parity
    int f = tid & 127;       // feature
    float acc = 0.f;
    int curbid = sb[half];

#pragma unroll 8
    for (int r = half; r < 128; r += 2) {
        int bv = sb[r];
        if (bv != curbid) {
            if (curbid >= 0) atomicAdd(&g_sums[curbid * D + f], acc);
            acc = 0.f;
            curbid = bv;
        }
        if (bv >= 0) acc += x[(size_t)(n0 + r) * D + f];
    }
    if (curbid >= 0) atomicAdd(&g_sums[curbid * D + f], acc);
}

// ---------------------------------------------------------------------------
// K3: C[g] = (sums[g]/cnt) @ W2^T + b
// ---------------------------------------------------------------------------
__global__ void k_ctx(const float* __restrict__ W, const float* __restrict__ b) {
    __shared__ float sm[D];
    int g = blockIdx.x, t = threadIdx.x;
    int s = g_segstart[g], e = g_segstart[g + 1];
    int cnt = e - s;
    float inv = 1.f / (float)(cnt > 0 ? cnt : 1);
    sm[t] = g_sums[g * D + t] * inv;
    __syncthreads();
    float c = b[t];
    const float* wrow = W + (size_t)t * 256 + 128;
#pragma unroll 8
    for (int k = 0; k < D; ++k) c += sm[k] * wrow[k];
    g_C[g * D + t] = c;
}

// ---------------------------------------------------------------------------
// K4: fp16x2 mma.sync GEMM  out[n] = x[n] @ W1^T + C[bid[n]]
// ks processed in pairs with next-pair register prefetch (distance 2).
// ---------------------------------------------------------------------------
#define STG_STRIDE 136
#define SMEM_BYTES (128 * STG_STRIDE * 4)

__global__ void __launch_bounds__(256, 2)
k_gemm(const float* __restrict__ x, const int* __restrict__ bid,
       float* __restrict__ out, int N) {
    extern __shared__ __align__(16) uint32_t sh[];
    uint32_t* shB = sh;                      // [8192] u32 fp16 B frags

    int tid = threadIdx.x;
    int w   = tid >> 5;
    int l   = tid & 31;
    int n0  = blockIdx.x * 128;

#pragma unroll
    for (int i = 0; i < 8; ++i) {
        int q = i * 256 + tid;
        *(uint4*)(shB + q * 4) = *(const uint4*)(g_Bf + q * 4);
    }
    __syncthreads();

    int g4 = l >> 2, c4 = l & 3;
    int r0 = n0 + w * 16 + g4;
    int r1 = r0 + 8;
    const float* p0 = x + (size_t)r0 * 128;
    const float* p1 = x + (size_t)r1 * 128;
    bool full = (n0 + 128) <= N;
    bool vr0 = full || (r0 < N), vr1 = full || (r1 < N);
    const float2 z2 = make_float2(0.f, 0.f);

    float acc[16][4];
#pragma unroll
    for (int na = 0; na < 16; ++na)
#pragma unroll
        for (int j = 0; j < 4; ++j) acc[na][j] = 0.f;

    // A buffers for a pair of ks steps: [s][4] float2
    float2 cur[2][4], nxt[2][4];

#define LOAD_PAIR(dst, kp)                                                     \
    do {                                                                       \
        _Pragma("unroll")                                                      \
        for (int s_ = 0; s_ < 2; ++s_) {                                       \
            int k0_ = ((kp) * 2 + s_) * 16 + 2 * c4;                           \
            dst[s_][0] = vr0 ? *(const float2*)(p0 + k0_)     : z2;            \
            dst[s_][1] = vr1 ? *(const float2*)(p1 + k0_)     : z2;            \
            dst[s_][2] = vr0 ? *(const float2*)(p0 + k0_ + 8) : z2;            \
            dst[s_][3] = vr1 ? *(const float2*)(p1 + k0_ + 8) : z2;            \
        }                                                                      \
    } while (0)

    LOAD_PAIR(cur, 0);

#pragma unroll
    for (int kp = 0; kp < 4; ++kp) {
        if (kp < 3) LOAD_PAIR(nxt, kp + 1);

#pragma unroll
        for (int s = 0; s < 2; ++s) {
            int ks = kp * 2 + s;
            uint32_t ahi[4], alo[4];
#pragma unroll
            for (int j = 0; j < 4; ++j) {
                float2 v = cur[s][j];
                uint32_t h = pack_f16(v.x, v.y);
                ahi[j] = h;
                alo[j] = pack_f16(v.x - lo_h(h), v.y - hi_h(h));
            }
            const uint32_t* bks = shB + ks * 16 * 64;
#pragma unroll
            for (int na = 0; na < 16; ++na) {
                uint2 bh = *(const uint2*)(bks + na * 64 + l * 2);
                uint32_t bhr[2] = {bh.x, bh.y};
                mma_f16(acc[na], ahi, bhr);
                mma_f16(acc[na], alo, bhr);
            }
        }
#pragma unroll
        for (int s = 0; s < 2; ++s)
#pragma unroll
            for (int j = 0; j < 4; ++j) cur[s][j] = nxt[s][j];
    }
#undef LOAD_PAIR

    // --- Epilogue: stage through smem, add C, store coalesced ---
    float* stg = (float*)sh;
    __syncthreads();
    {
        int rl0 = w * 16 + g4;
#pragma unroll
        for (int na = 0; na < 16; ++na) {
            int cb = na * 8 + 2 * c4;
            *(float2*)(stg + rl0 * STG_STRIDE + cb) =
                make_float2(acc[na][0], acc[na][1]);
            *(float2*)(stg + (rl0 + 8) * STG_STRIDE + cb) =
                make_float2(acc[na][2], acc[na][3]);
        }
    }
    __syncthreads();
    {
        int cw = l * 4;
#pragma unroll
        for (int it = 0; it < 16; ++it) {
            int rloc = it * 8 + w;
            int n = n0 + rloc;
            if (n < N) {
                float4 v = *(float4*)(stg + rloc * STG_STRIDE + cw);
                int gidx = bid[n];
                float4 cv = *(const float4*)(g_C + (size_t)gidx * 128 + cw);
                v.x += cv.x; v.y += cv.y; v.z += cv.z; v.w += cv.w;
                *(float4*)(out + (size_t)n * 128 + cw) = v;
            }
        }
    }
}

// ---------------------------------------------------------------------------
extern "C" void kernel_launch(void* const* d_in, const int* in_sizes, int n_in,
                              void* d_out, int out_size) {
    const float* x   = (const float*)d_in[0];
    const int*   bid = (const int*)  d_in[1];
    const float* W   = (const float*)d_in[2];
    const float* b   = (const float*)d_in[3];
    float* out = (float*)d_out;
    int N = in_sizes[1];

    cudaFuncSetAttribute(k_gemm, cudaFuncAttributeMaxDynamicSharedMemorySize, SMEM_BYTES);

    int tiles = (N + 127) / 128;
    k_prep<<<(N + 255) / 256, 256>>>(bid, N, W);
    k_sum<<<tiles, 256>>>(x, bid, N);
    k_ctx<<<G_NUM, 128>>>(W, b);
    k_gemm<<<tiles, 256, SMEM_BYTES>>>(x, bid, out, N);
}

// round 8
// speedup vs baseline: 1.1351x; 1.1351x over previous
#include <cuda_runtime.h>
#include <cuda_bf16.h>
#include <cuda_fp16.h>
#include <cstdint>

#define G_NUM 1024
#define D 128

// ---------------------------------------------------------------------------
// Device scratch
// ---------------------------------------------------------------------------
__device__ int   g_segstart[G_NUM + 1];
__device__ float g_sums[G_NUM * D];
__device__ float g_C[G_NUM * D];
// W1 (fp16) in COLUMN-PERMUTED mma B-fragment layout:
// frag kslot (2c4+j) <- actual col 16ks+4c4+j ; kslot (8+2c4+j) <- col 16ks+4c4+2+j
__device__ __align__(16) uint32_t g_Bf[8192];

// ---------------------------------------------------------------------------
// Helpers
// ---------------------------------------------------------------------------
__device__ __forceinline__ uint32_t pack_f16(float lo, float hi) {
    uint32_t r;
    asm("cvt.rn.f16x2.f32 %0, %1, %2;" : "=r"(r) : "f"(hi), "f"(lo));
    return r;
}
__device__ __forceinline__ float lo_h(uint32_t p) {
    return __half2float(__ushort_as_half((unsigned short)(p & 0xffff)));
}
__device__ __forceinline__ float hi_h(uint32_t p) {
    return __half2float(__ushort_as_half((unsigned short)(p >> 16)));
}

__device__ __forceinline__ void mma_f16(float* d, const uint32_t* a, const uint32_t* b) {
    asm volatile(
        "mma.sync.aligned.m16n8k16.row.col.f32.f16.f16.f32 "
        "{%0,%1,%2,%3}, {%4,%5,%6,%7}, {%8,%9}, {%0,%1,%2,%3};"
        : "+f"(d[0]), "+f"(d[1]), "+f"(d[2]), "+f"(d[3])
        : "r"(a[0]), "r"(a[1]), "r"(a[2]), "r"(a[3]), "r"(b[0]), "r"(b[1]));
}

// ---------------------------------------------------------------------------
// K1: zero sums + segment boundaries + W1 -> permuted fp16 B-fragments
// ---------------------------------------------------------------------------
__global__ void k_prep(const int* __restrict__ bid, int N, const float* __restrict__ W) {
    int i = blockIdx.x * blockDim.x + threadIdx.x;
    if (i < G_NUM * D) g_sums[i] = 0.f;
    if (i < N) {
        int b = bid[i];
        int prev = (i == 0) ? -1 : bid[i - 1];
        for (int g = prev + 1; g <= b; ++g) g_segstart[g] = i;
        if (i == N - 1)
            for (int g = b + 1; g <= G_NUM; ++g) g_segstart[g] = N;
    }
    if (i < 4096) {
        int ks = i >> 9;
        int na = (i >> 5) & 15;
        int l  = i & 31;
        int c  = l & 3;
        int n  = na * 8 + (l >> 2);
        int k0 = ks * 16 + 4 * c;          // permuted: lane owns 4 contiguous cols
        const float* wr = W + (size_t)n * 256;
        g_Bf[i * 2 + 0] = pack_f16(wr[k0],     wr[k0 + 1]);
        g_Bf[i * 2 + 1] = pack_f16(wr[k0 + 2], wr[k0 + 3]);
    }
}

// ---------------------------------------------------------------------------
// K2: tile-parallel segment sums, float4 loads.
// CTA = 256 rows, 256 thr: thread (h=t>>5, q=t&31) does rows h,h+8,...,
// features 4q..4q+3. Flush to g_sums at bid boundaries (atomicAdd).
// ---------------------------------------------------------------------------
__global__ void __launch_bounds__(256)
k_sum(const float* __restrict__ x, const int* __restrict__ bid, int N) {
    __shared__ int sb[256];
    int tid = threadIdx.x;
    int n0 = blockIdx.x * 256;
    sb[tid] = (n0 + tid < N) ? bid[n0 + tid] : -1;
    __syncthreads();

    int h = tid >> 5;
    int q = tid & 31;
    float4 acc = make_float4(0.f, 0.f, 0.f, 0.f);
    int curbid = sb[h];

#pragma unroll 8
    for (int r = h; r < 256; r += 8) {
        int bv = sb[r];
        if (bv != curbid) {
            if (curbid >= 0) {
                float* dst = &g_sums[curbid * D + q * 4];
                atomicAdd(dst + 0, acc.x); atomicAdd(dst + 1, acc.y);
                atomicAdd(dst + 2, acc.z); atomicAdd(dst + 3, acc.w);
            }
            acc = make_float4(0.f, 0.f, 0.f, 0.f);
            curbid = bv;
        }
        if (bv >= 0) {
            float4 v = *(const float4*)(x + (size_t)(n0 + r) * D + q * 4);
            acc.x += v.x; acc.y += v.y; acc.z += v.z; acc.w += v.w;
        }
    }
    if (curbid >= 0) {
        float* dst = &g_sums[curbid * D + q * 4];
        atomicAdd(dst + 0, acc.x); atomicAdd(dst + 1, acc.y);
        atomicAdd(dst + 2, acc.z); atomicAdd(dst + 3, acc.w);
    }
}

// ---------------------------------------------------------------------------
// K3: C[g] = (sums[g]/cnt) @ W2^T + b
// ---------------------------------------------------------------------------
__global__ void k_ctx(const float* __restrict__ W, const float* __restrict__ b) {
    __shared__ float sm[D];
    int g = blockIdx.x, t = threadIdx.x;
    int s = g_segstart[g], e = g_segstart[g + 1];
    int cnt = e - s;
    float inv = 1.f / (float)(cnt > 0 ? cnt : 1);
    sm[t] = g_sums[g * D + t] * inv;
    __syncthreads();
    float c = b[t];
    const float* wrow = W + (size_t)t * 256 + 128;
#pragma unroll 8
    for (int k = 0; k < D; ++k) c += sm[k] * wrow[k];
    g_C[g * D + t] = c;
}

// ---------------------------------------------------------------------------
// K4: fp16x2 mma.sync GEMM  out[n] = x[n] @ W1^T + C[bid[n]]
// A loads: one float4 per row per ks (column-permuted fragments).
// ks in pairs, register prefetch distance 2.
// ---------------------------------------------------------------------------
#define STG_STRIDE 136
#define SMEM_BYTES (128 * STG_STRIDE * 4)

__global__ void __launch_bounds__(256, 2)
k_gemm(const float* __restrict__ x, const int* __restrict__ bid,
       float* __restrict__ out, int N) {
    extern __shared__ __align__(16) uint32_t sh[];
    uint32_t* shB = sh;                      // [8192] u32 fp16 B frags

    int tid = threadIdx.x;
    int w   = tid >> 5;
    int l   = tid & 31;
    int n0  = blockIdx.x * 128;

#pragma unroll
    for (int i = 0; i < 8; ++i) {
        int q = i * 256 + tid;
        *(uint4*)(shB + q * 4) = *(const uint4*)(g_Bf + q * 4);
    }
    __syncthreads();

    int g4 = l >> 2, c4 = l & 3;
    int r0 = n0 + w * 16 + g4;
    int r1 = r0 + 8;
    const float* p0 = x + (size_t)r0 * 128;
    const float* p1 = x + (size_t)r1 * 128;
    bool full = (n0 + 128) <= N;
    bool vr0 = full || (r0 < N), vr1 = full || (r1 < N);
    const float4 z4 = make_float4(0.f, 0.f, 0.f, 0.f);

    float acc[16][4];
#pragma unroll
    for (int na = 0; na < 16; ++na)
#pragma unroll
        for (int j = 0; j < 4; ++j) acc[na][j] = 0.f;

    // A buffers for a pair of ks steps: [s][row] float4
    float4 cur[2][2], nxt[2][2];

#define LOAD_PAIR(dst, kp)                                                     \
    do {                                                                       \
        _Pragma("unroll")                                                      \
        for (int s_ = 0; s_ < 2; ++s_) {                                       \
            int k0_ = ((kp) * 2 + s_) * 16 + 4 * c4;                           \
            dst[s_][0] = vr0 ? *(const float4*)(p0 + k0_) : z4;                \
            dst[s_][1] = vr1 ? *(const float4*)(p1 + k0_) : z4;                \
        }                                                                      \
    } while (0)

    LOAD_PAIR(cur, 0);

#pragma unroll
    for (int kp = 0; kp < 4; ++kp) {
        if (kp < 3) LOAD_PAIR(nxt, kp + 1);

#pragma unroll
        for (int s = 0; s < 2; ++s) {
            int ks = kp * 2 + s;
            float4 u = cur[s][0];   // row r0: cols 4c4..4c4+3
            float4 v = cur[s][1];   // row r1
            uint32_t ahi[4], alo[4];
            ahi[0] = pack_f16(u.x, u.y);
            ahi[1] = pack_f16(v.x, v.y);
            ahi[2] = pack_f16(u.z, u.w);
            ahi[3] = pack_f16(v.z, v.w);
            alo[0] = pack_f16(u.x - lo_h(ahi[0]), u.y - hi_h(ahi[0]));
            alo[1] = pack_f16(v.x - lo_h(ahi[1]), v.y - hi_h(ahi[1]));
            alo[2] = pack_f16(u.z - lo_h(ahi[2]), u.w - hi_h(ahi[2]));
            alo[3] = pack_f16(v.z - lo_h(ahi[3]), v.w - hi_h(ahi[3]));

            const uint32_t* bks = shB + ks * 16 * 64;
#pragma unroll
            for (int na = 0; na < 16; ++na) {
                uint2 bh = *(const uint2*)(bks + na * 64 + l * 2);
                uint32_t bhr[2] = {bh.x, bh.y};
                mma_f16(acc[na], ahi, bhr);
                mma_f16(acc[na], alo, bhr);
            }
        }
#pragma unroll
        for (int s = 0; s < 2; ++s)
#pragma unroll
            for (int j = 0; j < 2; ++j) cur[s][j] = nxt[s][j];
    }
#undef LOAD_PAIR

    // --- Epilogue: stage through smem, add C, store coalesced ---
    float* stg = (float*)sh;
    __syncthreads();
    {
        int rl0 = w * 16 + g4;
#pragma unroll
        for (int na = 0; na < 16; ++na) {
            int cb = na * 8 + 2 * c4;
            *(float2*)(stg + rl0 * STG_STRIDE + cb) =
                make_float2(acc[na][0], acc[na][1]);
            *(float2*)(stg + (rl0 + 8) * STG_STRIDE + cb) =
                make_float2(acc[na][2], acc[na][3]);
        }
    }
    __syncthreads();
    {
        int cw = l * 4;
#pragma unroll
        for (int it = 0; it < 16; ++it) {
            int rloc = it * 8 + w;
            int n = n0 + rloc;
            if (n < N) {
                float4 v = *(float4*)(stg + rloc * STG_STRIDE + cw);
                int gidx = bid[n];
                float4 cv = *(const float4*)(g_C + (size_t)gidx * 128 + cw);
                v.x += cv.x; v.y += cv.y; v.z += cv.z; v.w += cv.w;
                *(float4*)(out + (size_t)n * 128 + cw) = v;
            }
        }
    }
}

// ---------------------------------------------------------------------------
extern "C" void kernel_launch(void* const* d_in, const int* in_sizes, int n_in,
                              void* d_out, int out_size) {
    const float* x   = (const float*)d_in[0];
    const int*   bid = (const int*)  d_in[1];
    const float* W   = (const float*)d_in[2];
    const float* b   = (const float*)d_in[3];
    float* out = (float*)d_out;
    int N = in_sizes[1];

    cudaFuncSetAttribute(k_gemm, cudaFuncAttributeMaxDynamicSharedMemorySize, SMEM_BYTES);

    k_prep<<<(N + 255) / 256, 256>>>(bid, N, W);
    k_sum<<<(N + 255) / 256, 256>>>(x, bid, N);
    k_ctx<<<G_NUM, 128>>>(W, b);
    k_gemm<<<(N + 127) / 128, 256, SMEM_BYTES>>>(x, bid, out, N);
}